// round 6
// baseline (speedup 1.0000x reference)
#include <cuda_runtime.h>
#include <math.h>

#define N_NODE 112
#define D_L1   256
#define D_L2   128
#define D_L3   64
#define N_BATCH 2048
#define KP1    56
#define KP2    28

// Batch-independent precomputed tensors
__device__ float g_H0[N_NODE * D_L1];    // H0[n][o] = Wp1[o][n] + bp1[o]
__device__ float g_E1[N_NODE * N_NODE];  // exp(relu(s0_i + t0_j + ba1))
__device__ float g_Wp2t[D_L1 * D_L2];    // Wp2 transposed: [d][c]

__device__ __forceinline__ float wsum(float v) {
#pragma unroll
    for (int s = 16; s; s >>= 1) v += __shfl_xor_sync(0xffffffffu, v, s);
    return v;
}

// ---------------------------------------------------------------- precompute
__global__ void preA(const float* __restrict__ Wp1, const float* __restrict__ bp1,
                     const float* __restrict__ Wp2) {
    int idx = blockIdx.x * blockDim.x + threadIdx.x;
    if (idx < N_NODE * D_L1) {
        int n = idx / D_L1, o = idx % D_L1;
        g_H0[idx] = Wp1[o * N_NODE + n] + bp1[o];
    }
    if (idx < D_L1 * D_L2) {
        int d = idx / D_L2, c = idx % D_L2;
        g_Wp2t[idx] = Wp2[c * D_L1 + d];
    }
}

__global__ void preB(const float* __restrict__ wa1, const float* __restrict__ wb1,
                     const float* __restrict__ ba1) {
    __shared__ float s0[N_NODE], t0[N_NODE];
    int tid = threadIdx.x, lane = tid & 31, wid = tid >> 5;
    for (int i = wid; i < N_NODE; i += 8) {
        float as = 0.f, at = 0.f;
        for (int o = lane; o < D_L1; o += 32) {
            float h = g_H0[i * D_L1 + o];
            as += h * wa1[o];
            at += h * wb1[o];
        }
        as = wsum(as); at = wsum(at);
        if (!lane) { s0[i] = as; t0[i] = at; }
    }
    __syncthreads();
    float ba = ba1[0];
    for (int idx = tid; idx < N_NODE * N_NODE; idx += blockDim.x) {
        int i = idx / N_NODE, j = idx % N_NODE;
        g_E1[idx] = expf(fmaxf(s0[i] + t0[j] + ba, 0.f));
    }
}

// ---------------------------------------------------------------- main megakernel
// smem plan (floats):
//   sW   [112][116]  @0       (later reused: sa [56][57] @0, sh2 [56][128] @3192)
//   sh1  [112][256]  @12992   (later reused: sho [56][128])
//   small arrays     @41664   (~2.5 KB)
//   sWp  [64][128]   @42304   (P5 staging chunk of g_Wp2t)
#define SW_OFF   0
#define SW_STR   116
#define SH1_OFF  12992
#define SMALL_OFF 41664
#define SWP_OFF  42304
#define SA_STR   57
#define SMEM_FLOATS (SWP_OFF + 64 * D_L2)
#define SMEM_BYTES (SMEM_FLOATS * 4)

__global__ void __launch_bounds__(512, 1) gnn_main(
    const float* __restrict__ x,
    const float* __restrict__ Wpool1, const float* __restrict__ bpool1,
    const float* __restrict__ bp2,
    const float* __restrict__ wa2, const float* __restrict__ wb2,
    const float* __restrict__ ba2,
    const float* __restrict__ Wpool2, const float* __restrict__ bpool2,
    const float* __restrict__ Wfc1, const float* __restrict__ bfc1,
    const float* __restrict__ Wfc2, const float* __restrict__ bfc2,
    float* __restrict__ out)
{
    extern __shared__ float smem[];
    float* sW    = smem + SW_OFF;
    float* sh1   = smem + SH1_OFF;
    float* ssig1 = smem + SMALL_OFF;          // 112
    int*   idx1  = (int*)(ssig1 + 112);       // 56
    float* val1  = (float*)(idx1 + 56);       // 56
    float* s2    = val1 + 56;                 // 56
    float* t2    = s2 + 56;                   // 56
    float* ssig2 = t2 + 56;                   // 56
    int*   idx2  = (int*)(ssig2 + 56);        // 28
    float* val2  = (float*)(idx2 + 28);       // 28
    float* smean = val2 + 28;                 // 128
    float* sfc   = smean + 128;               // 64
    float* sWp   = smem + SWP_OFF;            // [64][128] staged Wp2t chunk
    float* sa    = sW;                        // [56][57]
    float* sh2   = sW + 3192;                 // [56][128]
    float* sho   = sh1;                       // [56][128]

    const int tid = threadIdx.x, lane = tid & 31, wid = tid >> 5;
    const int b = blockIdx.x;
    const float* xb = x + (size_t)b * N_NODE * N_NODE;

    // ---- P0: W = rownorm(E1 .* x[b]) into sW (stride 116) ----
    for (int i = wid; i < N_NODE; i += 16) {
        float part = 0.f;
#pragma unroll
        for (int jj = 0; jj < 4; jj++) {
            int j = lane + jj * 32;
            if (j < N_NODE) {
                float u = g_E1[i * N_NODE + j] * xb[i * N_NODE + j];
                sW[i * SW_STR + j] = u;
                part += u;
            }
        }
        part = wsum(part);
        float inv = 1.f / part;
#pragma unroll
        for (int jj = 0; jj < 4; jj++) {
            int j = lane + jj * 32;
            if (j < N_NODE) sW[i * SW_STR + j] *= inv;
        }
    }
    __syncthreads();

    // ---- P1: h1 = relu(W @ H0 + H0)  [112][256] ----
    {
        const int o  = tid & 255;
        const int oh = tid >> 8;              // 0..1
        for (int ibb = 0; ibb < 4; ibb++) {
            const int i0 = (oh * 4 + ibb) * 14;
            float acc[14];
#pragma unroll
            for (int r = 0; r < 14; r++) acc[r] = g_H0[(i0 + r) * D_L1 + o];
            float h0 = g_H0[0 * D_L1 + o];
            float h1v = g_H0[1 * D_L1 + o];
            float h2v = g_H0[2 * D_L1 + o];
            float h3v = g_H0[3 * D_L1 + o];
#pragma unroll 2
            for (int k = 0; k < N_NODE; k += 4) {
                float n0 = 0.f, n1 = 0.f, n2 = 0.f, n3 = 0.f;
                if (k + 4 < N_NODE) {
                    n0 = g_H0[(k + 4) * D_L1 + o];
                    n1 = g_H0[(k + 5) * D_L1 + o];
                    n2 = g_H0[(k + 6) * D_L1 + o];
                    n3 = g_H0[(k + 7) * D_L1 + o];
                }
#pragma unroll
                for (int r = 0; r < 14; r++) {
                    const float4 w4 = *(const float4*)(sW + (i0 + r) * SW_STR + k);
                    acc[r] += w4.x * h0;
                    acc[r] += w4.y * h1v;
                    acc[r] += w4.z * h2v;
                    acc[r] += w4.w * h3v;
                }
                h0 = n0; h1v = n1; h2v = n2; h3v = n3;
            }
#pragma unroll
            for (int r = 0; r < 14; r++)
                sh1[(i0 + r) * D_L1 + o] = fmaxf(acc[r], 0.f);
        }
    }
    __syncthreads();

    // ---- P2: pool1 scores ----
    {
        float bp = bpool1[0];
        for (int i = wid; i < N_NODE; i += 16) {
            float a = 0.f;
#pragma unroll
            for (int oo = 0; oo < 8; oo++) {
                int o = lane + oo * 32;
                a += sh1[i * D_L1 + o] * Wpool1[o];
            }
            a = wsum(a);
            if (!lane) ssig1[i] = 1.f / (1.f + expf(-(a + bp)));
        }
    }
    __syncthreads();

    // ---- P3: top-56 via stable descending rank ----
    if (tid < N_NODE) {
        float sv = ssig1[tid];
        int rank = 0;
        for (int j = 0; j < N_NODE; j++) {
            float so = ssig1[j];
            rank += (so > sv) || (so == sv && j < tid);
        }
        if (rank < KP1) { idx1[rank] = tid; val1[rank] = sv; }
    }
    __syncthreads();

    // ---- P4: gather adjacency a1 = rownorm(x[gi][gj])  [56][57-padded] ----
    for (int i = wid; i < KP1; i += 16) {
        int gi = idx1[i];
        const float* xr = xb + gi * N_NODE;
        int j0 = lane, j1 = lane + 32;
        float v0 = xr[idx1[j0]];
        float v1 = (j1 < KP1) ? xr[idx1[j1]] : 0.f;
        float part = wsum(v0 + v1);
        float inv = 1.f / part;
        sa[i * SA_STR + j0] = v0 * inv;
        if (j1 < KP1) sa[i * SA_STR + j1] = v1 * inv;
    }
    // (P5's first __syncthreads orders P4's sa writes; sa @0..3192 and sWp @42304+
    //  are disjoint, and P5 writes sh2 @3192..10360 only at the end.)

    // ---- P5: h2 = (h1[gather]*val) @ Wp2^T + bp2  [56][128] ----
    // Identical FMA chains to R1 (sequential d=0..255, scalar FFMA); the only
    // change is operand sourcing: Wp2t staged into SMEM in 4 chunks of 64 rows.
    {
        const int c = tid & 127;
        const int q = tid >> 7;               // 0..3
        const int i0 = q * 14;
        int gr[14];
#pragma unroll
        for (int r = 0; r < 14; r++) gr[r] = idx1[i0 + r] * D_L1;
        float acc[14];
#pragma unroll
        for (int r = 0; r < 14; r++) acc[r] = 0.f;
        for (int t = 0; t < 4; t++) {
            __syncthreads();
            {   // stage Wp2t rows [t*64, (t+1)*64) -> sWp (8192 floats)
                const float4* src = (const float4*)(g_Wp2t + t * 64 * D_L2);
                float4* dst = (float4*)sWp;
#pragma unroll
                for (int v = 0; v < 4; v++) dst[tid + v * 512] = src[tid + v * 512];
            }
            __syncthreads();
            const int dbase = t * 64;
#pragma unroll 2
            for (int dd = 0; dd < 64; dd += 4) {
                float w0 = sWp[(dd + 0) * D_L2 + c];
                float w1 = sWp[(dd + 1) * D_L2 + c];
                float w2 = sWp[(dd + 2) * D_L2 + c];
                float w3 = sWp[(dd + 3) * D_L2 + c];
#pragma unroll
                for (int r = 0; r < 14; r++) {
                    const float4 h4 = *(const float4*)(sh1 + gr[r] + dbase + dd);
                    acc[r] += h4.x * w0;
                    acc[r] += h4.y * w1;
                    acc[r] += h4.z * w2;
                    acc[r] += h4.w * w3;
                }
            }
        }
        float bc = bp2[c];
#pragma unroll
        for (int r = 0; r < 14; r++)
            sh2[(i0 + r) * D_L2 + c] = val1[i0 + r] * acc[r] + bc;
    }
    __syncthreads();

    // ---- P6: s2/t2 attention halves ----
    for (int i = wid; i < KP1; i += 16) {
        float as = 0.f, at = 0.f;
#pragma unroll
        for (int cc = 0; cc < 4; cc++) {
            int c = lane + cc * 32;
            float h = sh2[i * D_L2 + c];
            as += h * wa2[c];
            at += h * wb2[c];
        }
        as = wsum(as); at = wsum(at);
        if (!lane) { s2[i] = as; t2[i] = at; }
    }
    __syncthreads();

    // ---- P7: att2 = rownorm(exp(relu(s2_i + t2_j + ba2)) .* a1), in place ----
    {
        float bav = ba2[0];
        for (int i = wid; i < KP1; i += 16) {
            float si = s2[i];
            int j0 = lane, j1 = lane + 32;
            float w0 = expf(fmaxf(si + t2[j0] + bav, 0.f)) * sa[i * SA_STR + j0];
            float w1 = (j1 < KP1)
                     ? expf(fmaxf(si + t2[j1] + bav, 0.f)) * sa[i * SA_STR + j1]
                     : 0.f;
            float part = wsum(w0 + w1);
            float inv = 1.f / part;
            sa[i * SA_STR + j0] = w0 * inv;
            if (j1 < KP1) sa[i * SA_STR + j1] = w1 * inv;
        }
    }
    __syncthreads();

    // ---- P8: h2out = relu(att2 @ h2 + h2) -> sho (overlays dead sh1) ----
    {
        const int c = tid & 127;
        const int q = tid >> 7;
        const int i0 = q * 14;
        float acc[14];
#pragma unroll
        for (int r = 0; r < 14; r++) acc[r] = sh2[(i0 + r) * D_L2 + c];
        for (int j = 0; j < KP1; j++) {
            float v = sh2[j * D_L2 + c];
#pragma unroll
            for (int r = 0; r < 14; r++)
                acc[r] += sa[(i0 + r) * SA_STR + j] * v;
        }
#pragma unroll
        for (int r = 0; r < 14; r++)
            sho[(i0 + r) * D_L2 + c] = fmaxf(acc[r], 0.f);
    }
    __syncthreads();

    // ---- P9: pool2 scores + top-28 (adjacency result is discarded -> skipped) ----
    {
        float bp = bpool2[0];
        for (int i = wid; i < KP1; i += 16) {
            float a = 0.f;
#pragma unroll
            for (int cc = 0; cc < 4; cc++) {
                int c = lane + cc * 32;
                a += sho[i * D_L2 + c] * Wpool2[c];
            }
            a = wsum(a);
            if (!lane) ssig2[i] = 1.f / (1.f + expf(-(a + bp)));
        }
    }
    __syncthreads();
    if (tid < KP1) {
        float sv = ssig2[tid];
        int rank = 0;
        for (int j = 0; j < KP1; j++) {
            float so = ssig2[j];
            rank += (so > sv) || (so == sv && j < tid);
        }
        if (rank < KP2) { idx2[rank] = tid; val2[rank] = sv; }
    }
    __syncthreads();

    // ---- P10: mean over the 28 kept (scaled) rows ----
    if (tid < D_L2) {
        float m = 0.f;
#pragma unroll
        for (int r = 0; r < KP2; r++)
            m += sho[idx2[r] * D_L2 + tid] * val2[r];
        smean[tid] = m * (1.f / (float)KP2);
    }
    __syncthreads();

    // ---- P11: fc1 relu ----
    if (tid < D_L3) {
        float a = bfc1[tid];
        for (int c = 0; c < D_L2; c++)
            a += smean[c] * Wfc1[tid * D_L2 + c];
        sfc[tid] = fmaxf(a, 0.f);
    }
    __syncthreads();

    // ---- P12: fc2 -> scalar ----
    if (wid == 0) {
        float a = sfc[lane] * Wfc2[lane] + sfc[lane + 32] * Wfc2[lane + 32];
        a = wsum(a);
        if (!lane) out[b] = a + bfc2[0];
    }
}

// ---------------------------------------------------------------- launch
extern "C" void kernel_launch(void* const* d_in, const int* in_sizes, int n_in,
                              void* d_out, int out_size) {
    const float* x      = (const float*)d_in[0];
    const float* Wp1    = (const float*)d_in[1];
    const float* bp1    = (const float*)d_in[2];
    const float* wa1    = (const float*)d_in[3];
    const float* wb1    = (const float*)d_in[4];
    const float* ba1    = (const float*)d_in[5];
    const float* Wpool1 = (const float*)d_in[6];
    const float* bpool1 = (const float*)d_in[7];
    const float* Wp2    = (const float*)d_in[8];
    const float* bp2    = (const float*)d_in[9];
    const float* wa2    = (const float*)d_in[10];
    const float* wb2    = (const float*)d_in[11];
    const float* ba2    = (const float*)d_in[12];
    const float* Wpool2 = (const float*)d_in[13];
    const float* bpool2 = (const float*)d_in[14];
    const float* Wfc1   = (const float*)d_in[15];
    const float* bfc1   = (const float*)d_in[16];
    const float* Wfc2   = (const float*)d_in[17];
    const float* bfc2   = (const float*)d_in[18];
    float* out = (float*)d_out;

    cudaFuncSetAttribute(gnn_main, cudaFuncAttributeMaxDynamicSharedMemorySize,
                         SMEM_BYTES);

    preA<<<128, 256>>>(Wp1, bp1, Wp2);
    preB<<<1, 256>>>(wa1, wb1, ba1);
    gnn_main<<<N_BATCH, 512, SMEM_BYTES>>>(
        x, Wpool1, bpool1, bp2, wa2, wb2, ba2,
        Wpool2, bpool2, Wfc1, bfc1, Wfc2, bfc2, out);
}

// round 7
// speedup vs baseline: 1.0445x; 1.0445x over previous
#include <cuda_runtime.h>
#include <math.h>

#define N_NODE 112
#define D_L1   256
#define D_L2   128
#define D_L3   64
#define N_BATCH 2048
#define KP1    56
#define KP2    28

// Batch-independent precomputed tensors
__device__ float g_H0[N_NODE * D_L1];    // H0[n][o] = Wp1[o][n] + bp1[o]
__device__ float g_E1[N_NODE * N_NODE];  // exp(relu(s0_i + t0_j + ba1))
__device__ float g_Wp2t[D_L1 * D_L2];    // Wp2 transposed: [d][c]

__device__ __forceinline__ float wsum(float v) {
#pragma unroll
    for (int s = 16; s; s >>= 1) v += __shfl_xor_sync(0xffffffffu, v, s);
    return v;
}

// ---------------------------------------------------------------- precompute
__global__ void preA(const float* __restrict__ Wp1, const float* __restrict__ bp1,
                     const float* __restrict__ Wp2) {
    int idx = blockIdx.x * blockDim.x + threadIdx.x;
    if (idx < N_NODE * D_L1) {
        int n = idx / D_L1, o = idx % D_L1;
        g_H0[idx] = Wp1[o * N_NODE + n] + bp1[o];
    }
    if (idx < D_L1 * D_L2) {
        int d = idx / D_L2, c = idx % D_L2;
        g_Wp2t[idx] = Wp2[c * D_L1 + d];
    }
}

__global__ void preB(const float* __restrict__ wa1, const float* __restrict__ wb1,
                     const float* __restrict__ ba1) {
    __shared__ float s0[N_NODE], t0[N_NODE];
    int tid = threadIdx.x, lane = tid & 31, wid = tid >> 5;
    for (int i = wid; i < N_NODE; i += 8) {
        float as = 0.f, at = 0.f;
        for (int o = lane; o < D_L1; o += 32) {
            float h = g_H0[i * D_L1 + o];
            as += h * wa1[o];
            at += h * wb1[o];
        }
        as = wsum(as); at = wsum(at);
        if (!lane) { s0[i] = as; t0[i] = at; }
    }
    __syncthreads();
    float ba = ba1[0];
    for (int idx = tid; idx < N_NODE * N_NODE; idx += blockDim.x) {
        int i = idx / N_NODE, j = idx % N_NODE;
        g_E1[idx] = expf(fmaxf(s0[i] + t0[j] + ba, 0.f));
    }
}

// ---------------------------------------------------------------- main megakernel
// smem plan (floats) — identical to R1:
//   sW   [112][116]  @0       (later reused: sa [56][57] @0, sh2 [56][128] @3192)
//   sh1  [112][256]  @12992   (later reused: sho [56][128])
//   small arrays     @41664   (~2.5 KB)
#define SW_OFF   0
#define SW_STR   116
#define SH1_OFF  12992
#define SMALL_OFF 41664
#define SA_STR   57
#define SMEM_FLOATS 42304
#define SMEM_BYTES (SMEM_FLOATS * 4)

__global__ void __launch_bounds__(1024, 1) gnn_main(
    const float* __restrict__ x,
    const float* __restrict__ Wpool1, const float* __restrict__ bpool1,
    const float* __restrict__ bp2,
    const float* __restrict__ wa2, const float* __restrict__ wb2,
    const float* __restrict__ ba2,
    const float* __restrict__ Wpool2, const float* __restrict__ bpool2,
    const float* __restrict__ Wfc1, const float* __restrict__ bfc1,
    const float* __restrict__ Wfc2, const float* __restrict__ bfc2,
    float* __restrict__ out)
{
    extern __shared__ float smem[];
    float* sW    = smem + SW_OFF;
    float* sh1   = smem + SH1_OFF;
    float* ssig1 = smem + SMALL_OFF;          // 112
    int*   idx1  = (int*)(ssig1 + 112);       // 56
    float* val1  = (float*)(idx1 + 56);       // 56
    float* s2    = val1 + 56;                 // 56
    float* t2    = s2 + 56;                   // 56
    float* ssig2 = t2 + 56;                   // 56
    int*   idx2  = (int*)(ssig2 + 56);        // 28
    float* val2  = (float*)(idx2 + 28);       // 28
    float* smean = val2 + 28;                 // 128
    float* sfc   = smean + 128;               // 64
    float* sa    = sW;                        // [56][57]
    float* sh2   = sW + 3192;                 // [56][128]
    float* sho   = sh1;                       // [56][128]

    const int tid = threadIdx.x, lane = tid & 31, wid = tid >> 5;  // 32 warps
    const int b = blockIdx.x;
    const float* xb = x + (size_t)b * N_NODE * N_NODE;

    // ---- P0: W = rownorm(E1 .* x[b]) into sW (stride 116) ----
    // Per-row arithmetic identical to R1; rows distributed over 32 warps.
    for (int i = wid; i < N_NODE; i += 32) {
        float part = 0.f;
#pragma unroll
        for (int jj = 0; jj < 4; jj++) {
            int j = lane + jj * 32;
            if (j < N_NODE) {
                float u = g_E1[i * N_NODE + j] * xb[i * N_NODE + j];
                sW[i * SW_STR + j] = u;
                part += u;
            }
        }
        part = wsum(part);
        float inv = 1.f / part;
#pragma unroll
        for (int jj = 0; jj < 4; jj++) {
            int j = lane + jj * 32;
            if (j < N_NODE) sW[i * SW_STR + j] *= inv;
        }
    }
    __syncthreads();

    // ---- P1: h1 = relu(W @ H0 + H0)  [112][256] ----
    // Per-element k-chain verbatim R1; each thread now owns 2 groups of 14 rows.
    {
        const int o  = tid & 255;
        const int oh = tid >> 8;              // 0..3
        for (int ibb = 0; ibb < 2; ibb++) {
            const int i0 = (oh * 2 + ibb) * 14;
            float acc[14];
#pragma unroll
            for (int r = 0; r < 14; r++) acc[r] = g_H0[(i0 + r) * D_L1 + o];
            float h0 = g_H0[0 * D_L1 + o];
            float h1v = g_H0[1 * D_L1 + o];
            float h2v = g_H0[2 * D_L1 + o];
            float h3v = g_H0[3 * D_L1 + o];
#pragma unroll 2
            for (int k = 0; k < N_NODE; k += 4) {
                float n0 = 0.f, n1 = 0.f, n2 = 0.f, n3 = 0.f;
                if (k + 4 < N_NODE) {
                    n0 = g_H0[(k + 4) * D_L1 + o];
                    n1 = g_H0[(k + 5) * D_L1 + o];
                    n2 = g_H0[(k + 6) * D_L1 + o];
                    n3 = g_H0[(k + 7) * D_L1 + o];
                }
#pragma unroll
                for (int r = 0; r < 14; r++) {
                    const float4 w4 = *(const float4*)(sW + (i0 + r) * SW_STR + k);
                    acc[r] += w4.x * h0;
                    acc[r] += w4.y * h1v;
                    acc[r] += w4.z * h2v;
                    acc[r] += w4.w * h3v;
                }
                h0 = n0; h1v = n1; h2v = n2; h3v = n3;
            }
#pragma unroll
            for (int r = 0; r < 14; r++)
                sh1[(i0 + r) * D_L1 + o] = fmaxf(acc[r], 0.f);
        }
    }
    __syncthreads();

    // ---- P2: pool1 scores ----
    {
        float bp = bpool1[0];
        for (int i = wid; i < N_NODE; i += 32) {
            float a = 0.f;
#pragma unroll
            for (int oo = 0; oo < 8; oo++) {
                int o = lane + oo * 32;
                a += sh1[i * D_L1 + o] * Wpool1[o];
            }
            a = wsum(a);
            if (!lane) ssig1[i] = 1.f / (1.f + expf(-(a + bp)));
        }
    }
    __syncthreads();

    // ---- P3: top-56 via stable descending rank ----
    if (tid < N_NODE) {
        float sv = ssig1[tid];
        int rank = 0;
        for (int j = 0; j < N_NODE; j++) {
            float so = ssig1[j];
            rank += (so > sv) || (so == sv && j < tid);
        }
        if (rank < KP1) { idx1[rank] = tid; val1[rank] = sv; }
    }
    __syncthreads();

    // ---- P4: gather adjacency a1 = rownorm(x[gi][gj])  [56][57-padded] ----
    for (int i = wid; i < KP1; i += 32) {
        int gi = idx1[i];
        const float* xr = xb + gi * N_NODE;
        int j0 = lane, j1 = lane + 32;
        float v0 = xr[idx1[j0]];
        float v1 = (j1 < KP1) ? xr[idx1[j1]] : 0.f;
        float part = wsum(v0 + v1);
        float inv = 1.f / part;
        sa[i * SA_STR + j0] = v0 * inv;
        if (j1 < KP1) sa[i * SA_STR + j1] = v1 * inv;
    }
    // (no sync needed: P5 touches disjoint smem, sync after P5 covers both)

    // ---- P5: h2 = (h1[gather]*val) @ Wp2^T + bp2  [56][128] ----
    // Per-element d-chain verbatim R1 (direct LDG of Wp2t); 8 groups x 7 rows.
    {
        const int c = tid & 127;
        const int q = tid >> 7;               // 0..7
        const int i0 = q * 7;
        int gr[7];
#pragma unroll
        for (int r = 0; r < 7; r++) gr[r] = idx1[i0 + r] * D_L1;
        float acc[7];
#pragma unroll
        for (int r = 0; r < 7; r++) acc[r] = 0.f;
#pragma unroll 2
        for (int d = 0; d < D_L1; d += 4) {
            float w0 = g_Wp2t[(d + 0) * D_L2 + c];
            float w1 = g_Wp2t[(d + 1) * D_L2 + c];
            float w2 = g_Wp2t[(d + 2) * D_L2 + c];
            float w3 = g_Wp2t[(d + 3) * D_L2 + c];
#pragma unroll
            for (int r = 0; r < 7; r++) {
                const float4 h4 = *(const float4*)(sh1 + gr[r] + d);
                acc[r] += h4.x * w0;
                acc[r] += h4.y * w1;
                acc[r] += h4.z * w2;
                acc[r] += h4.w * w3;
            }
        }
        float bc = bp2[c];
#pragma unroll
        for (int r = 0; r < 7; r++)
            sh2[(i0 + r) * D_L2 + c] = val1[i0 + r] * acc[r] + bc;
    }
    __syncthreads();

    // ---- P6: s2/t2 attention halves ----
    for (int i = wid; i < KP1; i += 32) {
        float as = 0.f, at = 0.f;
#pragma unroll
        for (int cc = 0; cc < 4; cc++) {
            int c = lane + cc * 32;
            float h = sh2[i * D_L2 + c];
            as += h * wa2[c];
            at += h * wb2[c];
        }
        as = wsum(as); at = wsum(at);
        if (!lane) { s2[i] = as; t2[i] = at; }
    }
    __syncthreads();

    // ---- P7: att2 = rownorm(exp(relu(s2_i + t2_j + ba2)) .* a1), in place ----
    {
        float bav = ba2[0];
        for (int i = wid; i < KP1; i += 32) {
            float si = s2[i];
            int j0 = lane, j1 = lane + 32;
            float w0 = expf(fmaxf(si + t2[j0] + bav, 0.f)) * sa[i * SA_STR + j0];
            float w1 = (j1 < KP1)
                     ? expf(fmaxf(si + t2[j1] + bav, 0.f)) * sa[i * SA_STR + j1]
                     : 0.f;
            float part = wsum(w0 + w1);
            float inv = 1.f / part;
            sa[i * SA_STR + j0] = w0 * inv;
            if (j1 < KP1) sa[i * SA_STR + j1] = w1 * inv;
        }
    }
    __syncthreads();

    // ---- P8: h2out = relu(att2 @ h2 + h2) -> sho (overlays dead sh1) ----
    // Per-element j-chain verbatim R1; 8 groups x 7 rows.
    {
        const int c = tid & 127;
        const int q = tid >> 7;               // 0..7
        const int i0 = q * 7;
        float acc[7];
#pragma unroll
        for (int r = 0; r < 7; r++) acc[r] = sh2[(i0 + r) * D_L2 + c];
        for (int j = 0; j < KP1; j++) {
            float v = sh2[j * D_L2 + c];
#pragma unroll
            for (int r = 0; r < 7; r++)
                acc[r] += sa[(i0 + r) * SA_STR + j] * v;
        }
#pragma unroll
        for (int r = 0; r < 7; r++)
            sho[(i0 + r) * D_L2 + c] = fmaxf(acc[r], 0.f);
    }
    __syncthreads();

    // ---- P9: pool2 scores + top-28 (adjacency result is discarded -> skipped) ----
    {
        float bp = bpool2[0];
        for (int i = wid; i < KP1; i += 32) {
            float a = 0.f;
#pragma unroll
            for (int cc = 0; cc < 4; cc++) {
                int c = lane + cc * 32;
                a += sho[i * D_L2 + c] * Wpool2[c];
            }
            a = wsum(a);
            if (!lane) ssig2[i] = 1.f / (1.f + expf(-(a + bp)));
        }
    }
    __syncthreads();
    if (tid < KP1) {
        float sv = ssig2[tid];
        int rank = 0;
        for (int j = 0; j < KP1; j++) {
            float so = ssig2[j];
            rank += (so > sv) || (so == sv && j < tid);
        }
        if (rank < KP2) { idx2[rank] = tid; val2[rank] = sv; }
    }
    __syncthreads();

    // ---- P10: mean over the 28 kept (scaled) rows ----
    if (tid < D_L2) {
        float m = 0.f;
#pragma unroll
        for (int r = 0; r < KP2; r++)
            m += sho[idx2[r] * D_L2 + tid] * val2[r];
        smean[tid] = m * (1.f / (float)KP2);
    }
    __syncthreads();

    // ---- P11: fc1 relu ----
    if (tid < D_L3) {
        float a = bfc1[tid];
        for (int c = 0; c < D_L2; c++)
            a += smean[c] * Wfc1[tid * D_L2 + c];
        sfc[tid] = fmaxf(a, 0.f);
    }
    __syncthreads();

    // ---- P12: fc2 -> scalar ----
    if (wid == 0) {
        float a = sfc[lane] * Wfc2[lane] + sfc[lane + 32] * Wfc2[lane + 32];
        a = wsum(a);
        if (!lane) out[b] = a + bfc2[0];
    }
}

// ---------------------------------------------------------------- launch
extern "C" void kernel_launch(void* const* d_in, const int* in_sizes, int n_in,
                              void* d_out, int out_size) {
    const float* x      = (const float*)d_in[0];
    const float* Wp1    = (const float*)d_in[1];
    const float* bp1    = (const float*)d_in[2];
    const float* wa1    = (const float*)d_in[3];
    const float* wb1    = (const float*)d_in[4];
    const float* ba1    = (const float*)d_in[5];
    const float* Wpool1 = (const float*)d_in[6];
    const float* bpool1 = (const float*)d_in[7];
    const float* Wp2    = (const float*)d_in[8];
    const float* bp2    = (const float*)d_in[9];
    const float* wa2    = (const float*)d_in[10];
    const float* wb2    = (const float*)d_in[11];
    const float* ba2    = (const float*)d_in[12];
    const float* Wpool2 = (const float*)d_in[13];
    const float* bpool2 = (const float*)d_in[14];
    const float* Wfc1   = (const float*)d_in[15];
    const float* bfc1   = (const float*)d_in[16];
    const float* Wfc2   = (const float*)d_in[17];
    const float* bfc2   = (const float*)d_in[18];
    float* out = (float*)d_out;

    cudaFuncSetAttribute(gnn_main, cudaFuncAttributeMaxDynamicSharedMemorySize,
                         SMEM_BYTES);

    preA<<<128, 256>>>(Wp1, bp1, Wp2);
    preB<<<1, 256>>>(wa1, wb1, ba1);
    gnn_main<<<N_BATCH, 1024, SMEM_BYTES>>>(
        x, Wpool1, bpool1, bp2, wa2, wb2, ba2,
        Wpool2, bpool2, Wfc1, bfc1, Wfc2, bfc2, out);
}

// round 9
// speedup vs baseline: 1.0544x; 1.0095x over previous
#include <cuda_runtime.h>
#include <math.h>

#define N_NODE 112
#define D_L1   256
#define D_L2   128
#define D_L3   64
#define N_BATCH 2048
#define KP1    56
#define KP2    28

// Batch-independent precomputed tensors
__device__ float g_H0[N_NODE * D_L1];    // H0[n][o] = Wp1[o][n] + bp1[o]
__device__ float g_E1[N_NODE * N_NODE];  // exp(relu(s0_i + t0_j + ba1))
__device__ float g_Wp2t[D_L1 * D_L2];    // Wp2 transposed: [d][c]

__device__ __forceinline__ float wsum(float v) {
#pragma unroll
    for (int s = 16; s; s >>= 1) v += __shfl_xor_sync(0xffffffffu, v, s);
    return v;
}

// ---------------------------------------------------------------- precompute
// Single kernel: all blocks fill g_H0/g_Wp2t; block 0 additionally computes
// s0/t0/E1 directly from Wp1/bp1 (same fp32 values and reduction order as the
// old preB reading g_H0 -> bitwise-identical E1).
__global__ void pre(const float* __restrict__ Wp1, const float* __restrict__ bp1,
                    const float* __restrict__ Wp2,
                    const float* __restrict__ wa1, const float* __restrict__ wb1,
                    const float* __restrict__ ba1) {
    int idx = blockIdx.x * blockDim.x + threadIdx.x;
    if (idx < N_NODE * D_L1) {
        int n = idx / D_L1, o = idx % D_L1;
        g_H0[idx] = Wp1[o * N_NODE + n] + bp1[o];
    }
    if (idx < D_L1 * D_L2) {
        int d = idx / D_L2, c = idx % D_L2;
        g_Wp2t[idx] = Wp2[c * D_L1 + d];
    }
    if (blockIdx.x == 0) {
        __shared__ float s0[N_NODE], t0[N_NODE];
        int tid = threadIdx.x, lane = tid & 31, wid = tid >> 5;  // 8 warps
        for (int i = wid; i < N_NODE; i += 8) {
            float as = 0.f, at = 0.f;
            for (int o = lane; o < D_L1; o += 32) {
                float h = Wp1[o * N_NODE + i] + bp1[o];   // == g_H0[i*D_L1+o]
                as += h * wa1[o];
                at += h * wb1[o];
            }
            as = wsum(as); at = wsum(at);
            if (!lane) { s0[i] = as; t0[i] = at; }
        }
        __syncthreads();
        float ba = ba1[0];
        for (int k = tid; k < N_NODE * N_NODE; k += blockDim.x) {
            int i = k / N_NODE, j = k % N_NODE;
            g_E1[k] = expf(fmaxf(s0[i] + t0[j] + ba, 0.f));
        }
    }
}

// ---------------------------------------------------------------- main megakernel
// smem plan (floats) — identical to R1:
//   sW   [112][116]  @0       (later reused: sa [56][57] @0, sh2 [56][128] @3192)
//   sh1  [112][256]  @12992   (later reused: sho [56][128])
//   small arrays     @41664   (~2.5 KB)
#define SW_OFF   0
#define SW_STR   116
#define SH1_OFF  12992
#define SMALL_OFF 41664
#define SA_STR   57
#define SMEM_FLOATS 42304
#define SMEM_BYTES (SMEM_FLOATS * 4)

__global__ void __launch_bounds__(1024, 1) gnn_main(
    const float* __restrict__ x,
    const float* __restrict__ Wpool1, const float* __restrict__ bpool1,
    const float* __restrict__ bp2,
    const float* __restrict__ wa2, const float* __restrict__ wb2,
    const float* __restrict__ ba2,
    const float* __restrict__ Wpool2, const float* __restrict__ bpool2,
    const float* __restrict__ Wfc1, const float* __restrict__ bfc1,
    const float* __restrict__ Wfc2, const float* __restrict__ bfc2,
    float* __restrict__ out)
{
    extern __shared__ float smem[];
    float* sW    = smem + SW_OFF;
    float* sh1   = smem + SH1_OFF;
    float* ssig1 = smem + SMALL_OFF;          // 112
    int*   idx1  = (int*)(ssig1 + 112);       // 56
    float* val1  = (float*)(idx1 + 56);       // 56
    float* s2    = val1 + 56;                 // 56
    float* t2    = s2 + 56;                   // 56
    float* ssig2 = t2 + 56;                   // 56
    int*   idx2  = (int*)(ssig2 + 56);        // 28
    float* val2  = (float*)(idx2 + 28);       // 28
    float* smean = val2 + 28;                 // 128
    float* sfc   = smean + 128;               // 64
    float* sa    = sW;                        // [56][57]
    float* sh2   = sW + 3192;                 // [56][128]
    float* sho   = sh1;                       // [56][128]

    const int tid = threadIdx.x, lane = tid & 31, wid = tid >> 5;  // 32 warps
    const int b = blockIdx.x;
    const float* xb = x + (size_t)b * N_NODE * N_NODE;

    // ---- P0: W = rownorm(E1 .* x[b]) into sW (stride 116) ----
    for (int i = wid; i < N_NODE; i += 32) {
        float part = 0.f;
#pragma unroll
        for (int jj = 0; jj < 4; jj++) {
            int j = lane + jj * 32;
            if (j < N_NODE) {
                float u = g_E1[i * N_NODE + j] * xb[i * N_NODE + j];
                sW[i * SW_STR + j] = u;
                part += u;
            }
        }
        part = wsum(part);
        float inv = 1.f / part;
#pragma unroll
        for (int jj = 0; jj < 4; jj++) {
            int j = lane + jj * 32;
            if (j < N_NODE) sW[i * SW_STR + j] *= inv;
        }
    }
    __syncthreads();

    // ---- P1: h1 = relu(W @ H0 + H0)  [112][256] ----
    // Both 14-row groups processed in one k-walk (28 accs); each acc's k-chain
    // is verbatim R1: acc = H0row; then += w[k]*H0[k][o] for k = 0..111 in order.
    {
        const int o  = tid & 255;
        const int oh = tid >> 8;              // 0..3
        const int iA = (oh * 2 + 0) * 14;
        const int iB = (oh * 2 + 1) * 14;
        float accA[14], accB[14];
#pragma unroll
        for (int r = 0; r < 14; r++) {
            accA[r] = g_H0[(iA + r) * D_L1 + o];
            accB[r] = g_H0[(iB + r) * D_L1 + o];
        }
        float h0 = g_H0[0 * D_L1 + o];
        float h1v = g_H0[1 * D_L1 + o];
        float h2v = g_H0[2 * D_L1 + o];
        float h3v = g_H0[3 * D_L1 + o];
#pragma unroll 2
        for (int k = 0; k < N_NODE; k += 4) {
            float n0 = 0.f, n1 = 0.f, n2 = 0.f, n3 = 0.f;
            if (k + 4 < N_NODE) {
                n0 = g_H0[(k + 4) * D_L1 + o];
                n1 = g_H0[(k + 5) * D_L1 + o];
                n2 = g_H0[(k + 6) * D_L1 + o];
                n3 = g_H0[(k + 7) * D_L1 + o];
            }
#pragma unroll
            for (int r = 0; r < 14; r++) {
                const float4 wA = *(const float4*)(sW + (iA + r) * SW_STR + k);
                accA[r] += wA.x * h0;
                accA[r] += wA.y * h1v;
                accA[r] += wA.z * h2v;
                accA[r] += wA.w * h3v;
            }
#pragma unroll
            for (int r = 0; r < 14; r++) {
                const float4 wB = *(const float4*)(sW + (iB + r) * SW_STR + k);
                accB[r] += wB.x * h0;
                accB[r] += wB.y * h1v;
                accB[r] += wB.z * h2v;
                accB[r] += wB.w * h3v;
            }
            h0 = n0; h1v = n1; h2v = n2; h3v = n3;
        }
#pragma unroll
        for (int r = 0; r < 14; r++) {
            sh1[(iA + r) * D_L1 + o] = fmaxf(accA[r], 0.f);
            sh1[(iB + r) * D_L1 + o] = fmaxf(accB[r], 0.f);
        }
    }
    __syncthreads();

    // ---- P2: pool1 scores ----
    {
        float bp = bpool1[0];
        for (int i = wid; i < N_NODE; i += 32) {
            float a = 0.f;
#pragma unroll
            for (int oo = 0; oo < 8; oo++) {
                int o = lane + oo * 32;
                a += sh1[i * D_L1 + o] * Wpool1[o];
            }
            a = wsum(a);
            if (!lane) ssig1[i] = 1.f / (1.f + expf(-(a + bp)));
        }
    }
    __syncthreads();

    // ---- P3: top-56 via stable descending rank ----
    if (tid < N_NODE) {
        float sv = ssig1[tid];
        int rank = 0;
        for (int j = 0; j < N_NODE; j++) {
            float so = ssig1[j];
            rank += (so > sv) || (so == sv && j < tid);
        }
        if (rank < KP1) { idx1[rank] = tid; val1[rank] = sv; }
    }
    __syncthreads();

    // ---- P4: gather adjacency a1 = rownorm(x[gi][gj])  [56][57-padded] ----
    for (int i = wid; i < KP1; i += 32) {
        int gi = idx1[i];
        const float* xr = xb + gi * N_NODE;
        int j0 = lane, j1 = lane + 32;
        float v0 = xr[idx1[j0]];
        float v1 = (j1 < KP1) ? xr[idx1[j1]] : 0.f;
        float part = wsum(v0 + v1);
        float inv = 1.f / part;
        sa[i * SA_STR + j0] = v0 * inv;
        if (j1 < KP1) sa[i * SA_STR + j1] = v1 * inv;
    }
    // (no sync needed: P5 writes sh2 only; sync after P5 orders both)

    // ---- P5: h2 = (h1[gather]*val) @ Wp2^T + bp2  [56][128] ----
    {
        const int c = tid & 127;
        const int q = tid >> 7;               // 0..7
        const int i0 = q * 7;
        int gr[7];
#pragma unroll
        for (int r = 0; r < 7; r++) gr[r] = idx1[i0 + r] * D_L1;
        float acc[7];
#pragma unroll
        for (int r = 0; r < 7; r++) acc[r] = 0.f;
#pragma unroll 2
        for (int d = 0; d < D_L1; d += 4) {
            float w0 = g_Wp2t[(d + 0) * D_L2 + c];
            float w1 = g_Wp2t[(d + 1) * D_L2 + c];
            float w2 = g_Wp2t[(d + 2) * D_L2 + c];
            float w3 = g_Wp2t[(d + 3) * D_L2 + c];
#pragma unroll
            for (int r = 0; r < 7; r++) {
                const float4 h4 = *(const float4*)(sh1 + gr[r] + d);
                acc[r] += h4.x * w0;
                acc[r] += h4.y * w1;
                acc[r] += h4.z * w2;
                acc[r] += h4.w * w3;
            }
        }
        float bc = bp2[c];
#pragma unroll
        for (int r = 0; r < 7; r++)
            sh2[(i0 + r) * D_L2 + c] = val1[i0 + r] * acc[r] + bc;
    }
    __syncthreads();

    // ---- P6: s2/t2 attention halves ----
    for (int i = wid; i < KP1; i += 32) {
        float as = 0.f, at = 0.f;
#pragma unroll
        for (int cc = 0; cc < 4; cc++) {
            int c = lane + cc * 32;
            float h = sh2[i * D_L2 + c];
            as += h * wa2[c];
            at += h * wb2[c];
        }
        as = wsum(as); at = wsum(at);
        if (!lane) { s2[i] = as; t2[i] = at; }
    }
    __syncthreads();

    // ---- P7: att2 = rownorm(exp(relu(s2_i + t2_j + ba2)) .* a1), in place ----
    {
        float bav = ba2[0];
        for (int i = wid; i < KP1; i += 32) {
            float si = s2[i];
            int j0 = lane, j1 = lane + 32;
            float w0 = expf(fmaxf(si + t2[j0] + bav, 0.f)) * sa[i * SA_STR + j0];
            float w1 = (j1 < KP1)
                     ? expf(fmaxf(si + t2[j1] + bav, 0.f)) * sa[i * SA_STR + j1]
                     : 0.f;
            float part = wsum(w0 + w1);
            float inv = 1.f / part;
            sa[i * SA_STR + j0] = w0 * inv;
            if (j1 < KP1) sa[i * SA_STR + j1] = w1 * inv;
        }
    }
    __syncthreads();

    // ---- P8: h2out = relu(att2 @ h2 + h2) -> sho (overlays dead sh1) ----
    {
        const int c = tid & 127;
        const int q = tid >> 7;               // 0..7
        const int i0 = q * 7;
        float acc[7];
#pragma unroll
        for (int r = 0; r < 7; r++) acc[r] = sh2[(i0 + r) * D_L2 + c];
        for (int j = 0; j < KP1; j++) {
            float v = sh2[j * D_L2 + c];
#pragma unroll
            for (int r = 0; r < 7; r++)
                acc[r] += sa[(i0 + r) * SA_STR + j] * v;
        }
#pragma unroll
        for (int r = 0; r < 7; r++)
            sho[(i0 + r) * D_L2 + c] = fmaxf(acc[r], 0.f);
    }
    __syncthreads();

    // ---- P9: pool2 scores + top-28 (adjacency result is discarded -> skipped) ----
    {
        float bp = bpool2[0];
        for (int i = wid; i < KP1; i += 32) {
            float a = 0.f;
#pragma unroll
            for (int cc = 0; cc < 4; cc++) {
                int c = lane + cc * 32;
                a += sho[i * D_L2 + c] * Wpool2[c];
            }
            a = wsum(a);
            if (!lane) ssig2[i] = 1.f / (1.f + expf(-(a + bp)));
        }
    }
    __syncthreads();
    if (tid < KP1) {
        float sv = ssig2[tid];
        int rank = 0;
        for (int j = 0; j < KP1; j++) {
            float so = ssig2[j];
            rank += (so > sv) || (so == sv && j < tid);
        }
        if (rank < KP2) { idx2[rank] = tid; val2[rank] = sv; }
    }
    __syncthreads();

    // ---- P10: mean over the 28 kept (scaled) rows ----
    if (tid < D_L2) {
        float m = 0.f;
#pragma unroll
        for (int r = 0; r < KP2; r++)
            m += sho[idx2[r] * D_L2 + tid] * val2[r];
        smean[tid] = m * (1.f / (float)KP2);
    }
    __syncthreads();

    // ---- P11: fc1 relu ----
    if (tid < D_L3) {
        float a = bfc1[tid];
        for (int c = 0; c < D_L2; c++)
            a += smean[c] * Wfc1[tid * D_L2 + c];
        sfc[tid] = fmaxf(a, 0.f);
    }
    __syncthreads();

    // ---- P12: fc2 -> scalar ----
    if (wid == 0) {
        float a = sfc[lane] * Wfc2[lane] + sfc[lane + 32] * Wfc2[lane + 32];
        a = wsum(a);
        if (!lane) out[b] = a + bfc2[0];
    }
}

// ---------------------------------------------------------------- launch
extern "C" void kernel_launch(void* const* d_in, const int* in_sizes, int n_in,
                              void* d_out, int out_size) {
    const float* x      = (const float*)d_in[0];
    const float* Wp1    = (const float*)d_in[1];
    const float* bp1    = (const float*)d_in[2];
    const float* wa1    = (const float*)d_in[3];
    const float* wb1    = (const float*)d_in[4];
    const float* ba1    = (const float*)d_in[5];
    const float* Wpool1 = (const float*)d_in[6];
    const float* bpool1 = (const float*)d_in[7];
    const float* Wp2    = (const float*)d_in[8];
    const float* bp2    = (const float*)d_in[9];
    const float* wa2    = (const float*)d_in[10];
    const float* wb2    = (const float*)d_in[11];
    const float* ba2    = (const float*)d_in[12];
    const float* Wpool2 = (const float*)d_in[13];
    const float* bpool2 = (const float*)d_in[14];
    const float* Wfc1   = (const float*)d_in[15];
    const float* bfc1   = (const float*)d_in[16];
    const float* Wfc2   = (const float*)d_in[17];
    const float* bfc2   = (const float*)d_in[18];
    float* out = (float*)d_out;

    cudaFuncSetAttribute(gnn_main, cudaFuncAttributeMaxDynamicSharedMemorySize,
                         SMEM_BYTES);

    pre<<<128, 256>>>(Wp1, bp1, Wp2, wa1, wb1, ba1);
    gnn_main<<<N_BATCH, 1024, SMEM_BYTES>>>(
        x, Wpool1, bpool1, bp2, wa2, wb2, ba2,
        Wpool2, bpool2, Wfc1, bfc1, Wfc2, bfc2, out);
}